// round 1
// baseline (speedup 1.0000x reference)
#include <cuda_runtime.h>
#include <cuda_bf16.h>
#include <cstdint>

// ---------------- problem constants ----------------
#define BS      4
#define LQ      4096
#define EMBED   256
#define NH      8
#define HD      32
#define LEVELS  4
#define NPTS    4
#define SUMP    16   // LEVELS*NPTS
#define LV      8500 // 80*80 + 40*40 + 20*20 + 10*10

// level geometry (compile-time)
__device__ __constant__ int c_H[LEVELS]  = {80, 40, 20, 10};
__device__ __constant__ int c_W[LEVELS]  = {80, 40, 20, 10};
__device__ __constant__ int c_VS[LEVELS] = {0, 6400, 8000, 8400};

// ---------------- scratch (static device globals; no allocation) ----------------
__device__ float g_v   [(size_t)BS * LV * EMBED];     // value @ W_v + b_v
__device__ float g_off [(size_t)BS * LQ * EMBED];     // query @ W_off + b_off (raw offsets)
__device__ float g_attn[(size_t)BS * LQ * NH * SUMP]; // query @ W_attn + b_attn (logits)
__device__ float g_mid [(size_t)BS * LQ * EMBED];     // sampled output before W_o

// ---------------- fp32 SGEMM: C = A[M,K] @ B[K,N] + bias[N] ----------------
// 64x64 tile, BK=16, 256 threads, 4x4 micro-tile per thread.
#define TBM 64
#define TBN 64
#define TBK 16

__global__ __launch_bounds__(256)
void sgemm_bias(const float* __restrict__ A, const float* __restrict__ B,
                const float* __restrict__ bias, float* __restrict__ C,
                int M, int N, int K)
{
    __shared__ float As[TBK][TBM];   // transposed A tile
    __shared__ float Bs[TBK][TBN];

    const int tid = threadIdx.x;
    const int bm  = blockIdx.y * TBM;
    const int bn  = blockIdx.x * TBN;
    const int tx  = tid & 15;        // 0..15 -> 4 cols each
    const int ty  = tid >> 4;        // 0..15 -> 4 rows each

    // load mapping
    const int arow = tid >> 2;           // 0..63
    const int acol = (tid & 3) << 2;     // 0,4,8,12
    const int brow = tid >> 4;           // 0..15
    const int bcol = (tid & 15) << 2;    // 0..60

    float acc[4][4] = {};

    for (int k0 = 0; k0 < K; k0 += TBK) {
        float4 av = make_float4(0.f, 0.f, 0.f, 0.f);
        if (bm + arow < M)
            av = *(const float4*)(A + (size_t)(bm + arow) * K + k0 + acol);
        As[acol + 0][arow] = av.x;
        As[acol + 1][arow] = av.y;
        As[acol + 2][arow] = av.z;
        As[acol + 3][arow] = av.w;

        float4 bv = *(const float4*)(B + (size_t)(k0 + brow) * N + bn + bcol);
        *(float4*)&Bs[brow][bcol] = bv;

        __syncthreads();

        #pragma unroll
        for (int kk = 0; kk < TBK; kk++) {
            float4 a4 = *(const float4*)&As[kk][ty * 4];
            float4 b4 = *(const float4*)&Bs[kk][tx * 4];
            float a[4] = {a4.x, a4.y, a4.z, a4.w};
            float b[4] = {b4.x, b4.y, b4.z, b4.w};
            #pragma unroll
            for (int i = 0; i < 4; i++)
                #pragma unroll
                for (int j = 0; j < 4; j++)
                    acc[i][j] = fmaf(a[i], b[j], acc[i][j]);
        }
        __syncthreads();
    }

    #pragma unroll
    for (int i = 0; i < 4; i++) {
        int r = bm + ty * 4 + i;
        if (r < M) {
            #pragma unroll
            for (int j = 0; j < 4; j++) {
                int c = bn + tx * 4 + j;
                C[(size_t)r * N + c] = acc[i][j] + bias[c];
            }
        }
    }
}

// ---------------- fused softmax + location + bilinear sampling ----------------
// One warp per (b, q, h). Lane = output channel (HD=32).
// Lanes 0..15 additionally own one sampling point each (SUMP=16) for the
// softmax / location computation; point parameters are broadcast via shuffles.
__global__ __launch_bounds__(256)
void msda_sample(const float* __restrict__ v,     // [BS, LV, EMBED]
                 const float* __restrict__ offr,  // [BS, LQ, EMBED]  (NH,SUMP,2)
                 const float* __restrict__ attnl, // [BS, LQ, NH*SUMP]
                 const float* __restrict__ refp,  // [BS, LQ, 4]
                 float* __restrict__ mid)         // [BS, LQ, EMBED]
{
    const unsigned FULL = 0xffffffffu;
    const int lane = threadIdx.x & 31;
    const int wid  = (blockIdx.x * blockDim.x + threadIdx.x) >> 5;
    // wid = ((b*LQ + q)*NH + h)
    const int h = wid & (NH - 1);
    const int q = (wid >> 3) & (LQ - 1);
    const int b = wid >> 15;

    const float4 ref = *(const float4*)(refp + ((size_t)b * LQ + q) * 4);

    // lanes 0..15: per-point offset + attention logit
    float offx = 0.f, offy = 0.f, logit = -1e30f;
    if (lane < SUMP) {
        const float* ob = offr + ((size_t)b * LQ + q) * EMBED + (h * SUMP + lane) * 2;
        offx  = ob[0];
        offy  = ob[1];
        logit = attnl[((size_t)b * LQ + q) * (NH * SUMP) + h * SUMP + lane];
    }

    // warp softmax over lanes 0..15 (group-of-16 butterfly)
    float m = logit;
    #pragma unroll
    for (int s = 8; s > 0; s >>= 1) m = fmaxf(m, __shfl_xor_sync(FULL, m, s));
    float e = (lane < SUMP) ? __expf(logit - m) : 0.f;
    float ssum = e;
    #pragma unroll
    for (int s = 8; s > 0; s >>= 1) ssum += __shfl_xor_sync(FULL, ssum, s);
    const float w = e / ssum;

    // sampling location for this lane's point
    // loc = ref.xy + off * (1/NPTS) * ref.zw * 0.5
    const float cx = ref.x + offx * 0.125f * ref.z;  // 0.25 * 0.5
    const float cy = ref.y + offy * 0.125f * ref.w;

    const float* vb = v + (size_t)b * LV * EMBED + h * HD + lane; // lane = channel
    float acc = 0.f;

    #pragma unroll
    for (int p = 0; p < SUMP; p++) {
        const float pcx = __shfl_sync(FULL, cx, p);
        const float pcy = __shfl_sync(FULL, cy, p);
        const float pw  = __shfl_sync(FULL, w,  p);
        const int l  = p >> 2;
        const int Hl = c_H[l], Wl = c_W[l], vs = c_VS[l];

        const float x = pcx * (float)Wl - 0.5f;
        const float y = pcy * (float)Hl - 0.5f;
        const float x0f = floorf(x), y0f = floorf(y);
        const int x0 = (int)x0f, y0 = (int)y0f;
        const float lx = x - x0f, ly = y - y0f;

        const float w00 = (1.f - lx) * (1.f - ly) * pw;
        const float w10 = lx * (1.f - ly) * pw;
        const float w01 = (1.f - lx) * ly * pw;
        const float w11 = lx * ly * pw;

        const bool vx0 = (x0 >= 0) && (x0 < Wl);
        const bool vx1 = (x0 + 1 >= 0) && (x0 + 1 < Wl);
        const bool vy0 = (y0 >= 0) && (y0 < Hl);
        const bool vy1 = (y0 + 1 >= 0) && (y0 + 1 < Hl);

        const size_t base = (size_t)vs * EMBED;
        if (vy0 && vx0) acc = fmaf(w00, vb[base + (size_t)(y0 * Wl + x0) * EMBED], acc);
        if (vy0 && vx1) acc = fmaf(w10, vb[base + (size_t)(y0 * Wl + x0 + 1) * EMBED], acc);
        if (vy1 && vx0) acc = fmaf(w01, vb[base + (size_t)((y0 + 1) * Wl + x0) * EMBED], acc);
        if (vy1 && vx1) acc = fmaf(w11, vb[base + (size_t)((y0 + 1) * Wl + x0 + 1) * EMBED], acc);
    }

    mid[((size_t)b * LQ + q) * EMBED + h * HD + lane] = acc;
}

// ---------------- launch ----------------
extern "C" void kernel_launch(void* const* d_in, const int* in_sizes, int n_in,
                              void* d_out, int out_size)
{
    const float* query  = (const float*)d_in[0];
    const float* refp   = (const float*)d_in[1];
    const float* value  = (const float*)d_in[2];
    const float* W_off  = (const float*)d_in[3];
    const float* b_off  = (const float*)d_in[4];
    const float* W_attn = (const float*)d_in[5];
    const float* b_attn = (const float*)d_in[6];
    const float* W_v    = (const float*)d_in[7];
    const float* b_v    = (const float*)d_in[8];
    const float* W_o    = (const float*)d_in[9];
    const float* b_o    = (const float*)d_in[10];
    float* out = (float*)d_out;

    float *gv, *goff, *gattn, *gmid;
    cudaGetSymbolAddress((void**)&gv,    g_v);
    cudaGetSymbolAddress((void**)&goff,  g_off);
    cudaGetSymbolAddress((void**)&gattn, g_attn);
    cudaGetSymbolAddress((void**)&gmid,  g_mid);

    const int MV = BS * LV;   // 34000
    const int MQ = BS * LQ;   // 16384

    // 1) v = value @ W_v + b_v          [34000, 256]
    sgemm_bias<<<dim3(EMBED / TBN, (MV + TBM - 1) / TBM), 256>>>(
        value, W_v, b_v, gv, MV, EMBED, EMBED);

    // 2) off = query @ W_off + b_off    [16384, 256]
    sgemm_bias<<<dim3(EMBED / TBN, MQ / TBM), 256>>>(
        query, W_off, b_off, goff, MQ, EMBED, EMBED);

    // 3) attn logits = query @ W_attn + b_attn   [16384, 128]
    sgemm_bias<<<dim3((NH * SUMP) / TBN, MQ / TBM), 256>>>(
        query, W_attn, b_attn, gattn, MQ, NH * SUMP, EMBED);

    // 4) fused softmax + bilinear sampling -> g_mid [16384, 256]
    {
        const int total_warps = BS * LQ * NH;          // 131072
        const int threads = 256;                        // 8 warps/block
        const int blocks = total_warps / (threads / 32);
        msda_sample<<<blocks, threads>>>(gv, goff, gattn, refp, gmid);
    }

    // 5) out = g_mid @ W_o + b_o        [16384, 256]
    sgemm_bias<<<dim3(EMBED / TBN, MQ / TBM), 256>>>(
        gmid, W_o, b_o, out, MQ, EMBED, EMBED);
}

// round 3
// speedup vs baseline: 1.4622x; 1.4622x over previous
#include <cuda_runtime.h>
#include <cuda_bf16.h>
#include <cstdint>

// ---------------- problem constants ----------------
#define BS      4
#define LQ      4096
#define EMBED   256
#define NH      8
#define HD      32
#define LEVELS  4
#define NPTS    4
#define SUMP    16   // LEVELS*NPTS
#define LV      8500 // 80*80 + 40*40 + 20*20 + 10*10

// ---------------- scratch (static device globals; no allocation) ----------------
__device__ float g_v   [(size_t)BS * LV * EMBED];     // value @ W_v + b_v
__device__ float g_off [(size_t)BS * LQ * EMBED];     // query @ W_off + b_off (raw offsets)
__device__ float g_attn[(size_t)BS * LQ * NH * SUMP]; // query @ W_attn + b_attn (logits)
__device__ float g_mid [(size_t)BS * LQ * EMBED];     // sampled output before W_o

// ---------------- fp32 SGEMM: C = A[M,K] @ B[K,N] + bias[N] ----------------
// 128x128 tile, BK=16, 256 threads, 8x8 micro-tile in 4 quadrants.
#define BM 128
#define BN 128
#define BK 16

__global__ __launch_bounds__(256)
void sgemm_bias(const float* __restrict__ A, const float* __restrict__ B,
                const float* __restrict__ bias, float* __restrict__ C,
                int M, int N, int K)
{
    __shared__ float As[BK][BM];   // A tile, transposed (k-major)
    __shared__ float Bs[BK][BN];

    const int tid = threadIdx.x;
    const int bm  = blockIdx.y * BM;
    const int bn  = blockIdx.x * BN;

    const int tx = tid & 15;   // 0..15
    const int ty = tid >> 4;   // 0..15
    const int r0 = ty * 4;           // quadrant rows
    const int r1 = ty * 4 + 64;
    const int c0 = tx * 4;           // quadrant cols
    const int c1 = tx * 4 + 64;

    float acc[2][2][4][4] = {};

    for (int k0 = 0; k0 < K; k0 += BK) {
        // ---- load A tile: 128 rows x 16 cols, 2 float4 per thread ----
        #pragma unroll
        for (int i = 0; i < 2; i++) {
            int flat = tid + i * 256;           // 0..511
            int row  = flat >> 2;               // 0..127
            int col4 = (flat & 3) << 2;         // 0,4,8,12
            float4 av = make_float4(0.f, 0.f, 0.f, 0.f);
            if (bm + row < M)
                av = *(const float4*)(A + (size_t)(bm + row) * K + k0 + col4);
            As[col4 + 0][row] = av.x;
            As[col4 + 1][row] = av.y;
            As[col4 + 2][row] = av.z;
            As[col4 + 3][row] = av.w;
        }
        // ---- load B tile: 16 rows x 128 cols, 2 float4 per thread ----
        #pragma unroll
        for (int i = 0; i < 2; i++) {
            int flat = tid + i * 256;
            int row  = flat >> 5;               // 0..15
            int col  = (flat & 31) << 2;        // 0..124
            *(float4*)&Bs[row][col] =
                *(const float4*)(B + (size_t)(k0 + row) * N + bn + col);
        }
        __syncthreads();

        #pragma unroll
        for (int kk = 0; kk < BK; kk++) {
            float4 a0 = *(const float4*)&As[kk][r0];
            float4 a1 = *(const float4*)&As[kk][r1];
            float4 b0 = *(const float4*)&Bs[kk][c0];
            float4 b1 = *(const float4*)&Bs[kk][c1];
            float ar[2][4] = {{a0.x, a0.y, a0.z, a0.w}, {a1.x, a1.y, a1.z, a1.w}};
            float br[2][4] = {{b0.x, b0.y, b0.z, b0.w}, {b1.x, b1.y, b1.z, b1.w}};
            #pragma unroll
            for (int qi = 0; qi < 2; qi++)
                #pragma unroll
                for (int qj = 0; qj < 2; qj++)
                    #pragma unroll
                    for (int i = 0; i < 4; i++)
                        #pragma unroll
                        for (int j = 0; j < 4; j++)
                            acc[qi][qj][i][j] = fmaf(ar[qi][i], br[qj][j], acc[qi][qj][i][j]);
        }
        __syncthreads();
    }

    // ---- epilogue: add bias, store float4 ----
    #pragma unroll
    for (int qi = 0; qi < 2; qi++) {
        #pragma unroll
        for (int i = 0; i < 4; i++) {
            int r = bm + (qi ? r1 : r0) + i;
            if (r >= M) continue;
            #pragma unroll
            for (int qj = 0; qj < 2; qj++) {
                int c = bn + (qj ? c1 : c0);
                float4 bv = *(const float4*)(bias + c);
                float4 o;
                o.x = acc[qi][qj][i][0] + bv.x;
                o.y = acc[qi][qj][i][1] + bv.y;
                o.z = acc[qi][qj][i][2] + bv.z;
                o.w = acc[qi][qj][i][3] + bv.w;
                *(float4*)(C + (size_t)r * N + c) = o;
            }
        }
    }
}

// ---------------- fused softmax + location + bilinear sampling ----------------
// One warp per (b, q, h). Lane = output channel (HD=32).
// Lanes 0..15 precompute their point's clamped corner offsets (int4) and
// validity-zeroed attention-premultiplied weights (float4) into smem; the
// 16-point loop is then 2 broadcast LDS.128 + 4 coalesced LDG + 4 FMA.
// NOTE: the softmax shuffles execute only on lanes 0..15, so the shuffle
// mask MUST be 0xffff (naming inactive lanes in the mask deadlocks).
__global__ __launch_bounds__(256)
void msda_sample(const float* __restrict__ v,     // [BS, LV, EMBED]
                 const float* __restrict__ offr,  // [BS, LQ, EMBED]  (NH,SUMP,2)
                 const float* __restrict__ attnl, // [BS, LQ, NH*SUMP]
                 const float* __restrict__ refp,  // [BS, LQ, 4]
                 float* __restrict__ mid)         // [BS, LQ, EMBED]
{
    __shared__ int4   s_idx[8][SUMP];
    __shared__ float4 s_w  [8][SUMP];

    const unsigned HALF = 0x0000ffffu;   // lanes 0..15 only
    const int lane = threadIdx.x & 31;
    const int warp = threadIdx.x >> 5;
    const int wid  = (blockIdx.x * blockDim.x + threadIdx.x) >> 5;
    // wid = ((b*LQ + q)*NH + h)
    const int h = wid & (NH - 1);
    const int q = (wid >> 3) & (LQ - 1);
    const int b = wid >> 15;

    if (lane < SUMP) {
        const float4 ref = *(const float4*)(refp + ((size_t)b * LQ + q) * 4);
        const float* ob = offr + ((size_t)b * LQ + q) * EMBED + (h * SUMP + lane) * 2;
        const float offx = ob[0];
        const float offy = ob[1];
        const float logit = attnl[((size_t)b * LQ + q) * (NH * SUMP) + h * SUMP + lane];

        // softmax over the 16 active lanes (xor butterfly within the 16-group)
        float m = logit;
        #pragma unroll
        for (int s = 8; s > 0; s >>= 1) m = fmaxf(m, __shfl_xor_sync(HALF, m, s));
        float e = __expf(logit - m);
        float ssum = e;
        #pragma unroll
        for (int s = 8; s > 0; s >>= 1) ssum += __shfl_xor_sync(HALF, ssum, s);
        const float pw = e / ssum;

        // sampling location: loc = ref.xy + off * (1/NPTS) * ref.zw * 0.5
        const float cx = ref.x + offx * 0.125f * ref.z;
        const float cy = ref.y + offy * 0.125f * ref.w;

        const int l  = lane >> 2;
        const int Wl = 80 >> l, Hl = 80 >> l;            // 80,40,20,10
        const int vs = (l == 0) ? 0 : (l == 1) ? 6400 : (l == 2) ? 8000 : 8400;

        const float x = cx * (float)Wl - 0.5f;
        const float y = cy * (float)Hl - 0.5f;
        const float x0f = floorf(x), y0f = floorf(y);
        const int x0 = (int)x0f, y0 = (int)y0f;
        const float lx = x - x0f, ly = y - y0f;

        const float vx0 = (x0 >= 0 && x0 < Wl)         ? 1.f : 0.f;
        const float vx1 = (x0 + 1 >= 0 && x0 + 1 < Wl) ? 1.f : 0.f;
        const float vy0 = (y0 >= 0 && y0 < Hl)         ? 1.f : 0.f;
        const float vy1 = (y0 + 1 >= 0 && y0 + 1 < Hl) ? 1.f : 0.f;

        const int xc0 = min(max(x0, 0), Wl - 1);
        const int xc1 = min(max(x0 + 1, 0), Wl - 1);
        const int yc0 = min(max(y0, 0), Hl - 1);
        const int yc1 = min(max(y0 + 1, 0), Hl - 1);

        int4 idx;
        idx.x = (vs + yc0 * Wl + xc0) * EMBED;
        idx.y = (vs + yc0 * Wl + xc1) * EMBED;
        idx.z = (vs + yc1 * Wl + xc0) * EMBED;
        idx.w = (vs + yc1 * Wl + xc1) * EMBED;

        float4 ww;
        ww.x = (1.f - lx) * (1.f - ly) * pw * (vx0 * vy0);
        ww.y = lx * (1.f - ly) * pw * (vx1 * vy0);
        ww.z = (1.f - lx) * ly * pw * (vx0 * vy1);
        ww.w = lx * ly * pw * (vx1 * vy1);

        s_idx[warp][lane] = idx;
        s_w  [warp][lane] = ww;
    }
    __syncwarp();

    const float* vb = v + (size_t)b * LV * EMBED + h * HD + lane; // lane = channel
    float acc = 0.f;

    #pragma unroll
    for (int p = 0; p < SUMP; p++) {
        const int4   id = s_idx[warp][p];
        const float4 ww = s_w  [warp][p];
        acc = fmaf(ww.x, __ldg(vb + id.x), acc);
        acc = fmaf(ww.y, __ldg(vb + id.y), acc);
        acc = fmaf(ww.z, __ldg(vb + id.z), acc);
        acc = fmaf(ww.w, __ldg(vb + id.w), acc);
    }

    mid[((size_t)b * LQ + q) * EMBED + h * HD + lane] = acc;
}

// ---------------- launch ----------------
extern "C" void kernel_launch(void* const* d_in, const int* in_sizes, int n_in,
                              void* d_out, int out_size)
{
    const float* query  = (const float*)d_in[0];
    const float* refp   = (const float*)d_in[1];
    const float* value  = (const float*)d_in[2];
    const float* W_off  = (const float*)d_in[3];
    const float* b_off  = (const float*)d_in[4];
    const float* W_attn = (const float*)d_in[5];
    const float* b_attn = (const float*)d_in[6];
    const float* W_v    = (const float*)d_in[7];
    const float* b_v    = (const float*)d_in[8];
    const float* W_o    = (const float*)d_in[9];
    const float* b_o    = (const float*)d_in[10];
    float* out = (float*)d_out;

    float *gv, *goff, *gattn, *gmid;
    cudaGetSymbolAddress((void**)&gv,    g_v);
    cudaGetSymbolAddress((void**)&goff,  g_off);
    cudaGetSymbolAddress((void**)&gattn, g_attn);
    cudaGetSymbolAddress((void**)&gmid,  g_mid);

    const int MV = BS * LV;   // 34000
    const int MQ = BS * LQ;   // 16384

    // 1) v = value @ W_v + b_v          [34000, 256]
    sgemm_bias<<<dim3(EMBED / BN, (MV + BM - 1) / BM), 256>>>(
        value, W_v, b_v, gv, MV, EMBED, EMBED);

    // 2) off = query @ W_off + b_off    [16384, 256]
    sgemm_bias<<<dim3(EMBED / BN, MQ / BM), 256>>>(
        query, W_off, b_off, goff, MQ, EMBED, EMBED);

    // 3) attn logits = query @ W_attn + b_attn   [16384, 128]
    sgemm_bias<<<dim3((NH * SUMP) / BN, MQ / BM), 256>>>(
        query, W_attn, b_attn, gattn, MQ, NH * SUMP, EMBED);

    // 4) fused softmax + bilinear sampling -> g_mid [16384, 256]
    {
        const int total_warps = BS * LQ * NH;          // 131072
        const int threads = 256;                        // 8 warps/block
        const int blocks = total_warps / (threads / 32);
        msda_sample<<<blocks, threads>>>(gv, goff, gattn, refp, gmid);
    }

    // 5) out = g_mid @ W_o + b_o        [16384, 256]
    sgemm_bias<<<dim3(EMBED / BN, MQ / BM), 256>>>(
        gmid, W_o, b_o, out, MQ, EMBED, EMBED);
}

// round 5
// speedup vs baseline: 1.6657x; 1.1391x over previous
#include <cuda_runtime.h>
#include <cuda_bf16.h>
#include <cstdint>

// ---------------- problem constants ----------------
#define BS      4
#define LQ      4096
#define EMBED   256
#define NH      8
#define HD      32
#define LEVELS  4
#define NPTS    4
#define SUMP    16   // LEVELS*NPTS
#define LV      8500 // 80*80 + 40*40 + 20*20 + 10*10

// ---------------- scratch (static device globals; no allocation) ----------------
__device__ float g_v   [(size_t)BS * LV * EMBED];     // value @ W_v + b_v
__device__ float g_off [(size_t)BS * LQ * EMBED];     // query @ W_off + b_off (raw offsets)
__device__ float g_attn[(size_t)BS * LQ * NH * SUMP]; // query @ W_attn + b_attn (logits)
__device__ float g_mid [(size_t)BS * LQ * EMBED];     // sampled output before W_o

// ---------------- 3xTF32 tensor-core GEMM: C = A[M,K] @ B[K,N] + bias[N] --------
// 128x128 block tile, BK=16, 256 threads = 8 warps in 2x4 grid, warp tile 64x32.
// Error-compensated tf32 (Ootomo): D += Ahi*Bhi + Ahi*Blo + Alo*Bhi  (fp32-like).
#define BM 128
#define BN 128
#define BK 16
#define A_STRIDE 20    // BK+4
#define B_STRIDE 136   // BN+8

__device__ __forceinline__ void mma_tf32(float* d, const uint32_t* a, const uint32_t* b)
{
    asm volatile(
        "mma.sync.aligned.m16n8k8.row.col.f32.tf32.tf32.f32 "
        "{%0,%1,%2,%3}, {%4,%5,%6,%7}, {%8,%9}, {%0,%1,%2,%3};\n"
        : "+f"(d[0]), "+f"(d[1]), "+f"(d[2]), "+f"(d[3])
        : "r"(a[0]), "r"(a[1]), "r"(a[2]), "r"(a[3]),
          "r"(b[0]), "r"(b[1]));
}

__device__ __forceinline__ uint32_t f2tf32(float x)
{
    uint32_t r;
    asm("cvt.rna.tf32.f32 %0, %1;" : "=r"(r) : "f"(x));
    return r;
}

__global__ __launch_bounds__(256)
void gemm_3xtf32_bias(const float* __restrict__ A, const float* __restrict__ B,
                      const float* __restrict__ bias, float* __restrict__ C,
                      int M, int N, int K)
{
    __shared__ float As[BM][A_STRIDE];
    __shared__ float Bs[BK][B_STRIDE];

    const int tid  = threadIdx.x;
    const int lane = tid & 31;
    const int wrp  = tid >> 5;          // 0..7
    const int wy   = wrp >> 2;          // 0..1 : row group of 64
    const int wx   = wrp & 3;           // 0..3 : col group of 32
    const int bm   = blockIdx.y * BM;
    const int bn   = blockIdx.x * BN;

    const int lq = lane >> 2;           // 0..7
    const int lr = lane & 3;            // 0..3

    float acc[4][4][4] = {};            // [mt][nt][c0..c3]

    for (int k0 = 0; k0 < K; k0 += BK) {
        // ---- load A tile: 128 rows x 16 cols (2 float4 per thread) ----
        #pragma unroll
        for (int i = 0; i < 2; i++) {
            int flat = tid + i * 256;
            int row  = flat >> 2;            // 0..127
            int col4 = (flat & 3) << 2;      // 0,4,8,12
            float4 av = make_float4(0.f, 0.f, 0.f, 0.f);
            if (bm + row < M)
                av = *(const float4*)(A + (size_t)(bm + row) * K + k0 + col4);
            *(float4*)&As[row][col4] = av;
        }
        // ---- load B tile: 16 rows x 128 cols (2 float4 per thread) ----
        #pragma unroll
        for (int i = 0; i < 2; i++) {
            int flat = tid + i * 256;
            int row  = flat >> 5;            // 0..15
            int col  = (flat & 31) << 2;     // 0..124
            *(float4*)&Bs[row][col] =
                *(const float4*)(B + (size_t)(k0 + row) * N + bn + col);
        }
        __syncthreads();

        #pragma unroll
        for (int k8 = 0; k8 < BK; k8 += 8) {
            // A fragments (hi/lo): 4 m-tiles of 16 rows
            uint32_t ahi[4][4], alo[4][4];
            #pragma unroll
            for (int mt = 0; mt < 4; mt++) {
                int r = wy * 64 + mt * 16 + lq;
                float a0 = As[r    ][k8 + lr    ];
                float a1 = As[r + 8][k8 + lr    ];
                float a2 = As[r    ][k8 + lr + 4];
                float a3 = As[r + 8][k8 + lr + 4];
                ahi[mt][0] = f2tf32(a0); alo[mt][0] = __float_as_uint(a0 - __uint_as_float(ahi[mt][0]));
                ahi[mt][1] = f2tf32(a1); alo[mt][1] = __float_as_uint(a1 - __uint_as_float(ahi[mt][1]));
                ahi[mt][2] = f2tf32(a2); alo[mt][2] = __float_as_uint(a2 - __uint_as_float(ahi[mt][2]));
                ahi[mt][3] = f2tf32(a3); alo[mt][3] = __float_as_uint(a3 - __uint_as_float(ahi[mt][3]));
            }
            // B fragments (hi/lo): 4 n-tiles of 8 cols
            uint32_t bhi[4][2], blo[4][2];
            #pragma unroll
            for (int nt = 0; nt < 4; nt++) {
                int c = wx * 32 + nt * 8 + lq;
                float b0 = Bs[k8 + lr    ][c];
                float b1 = Bs[k8 + lr + 4][c];
                bhi[nt][0] = f2tf32(b0); blo[nt][0] = __float_as_uint(b0 - __uint_as_float(bhi[nt][0]));
                bhi[nt][1] = f2tf32(b1); blo[nt][1] = __float_as_uint(b1 - __uint_as_float(bhi[nt][1]));
            }
            #pragma unroll
            for (int mt = 0; mt < 4; mt++)
                #pragma unroll
                for (int nt = 0; nt < 4; nt++) {
                    mma_tf32(acc[mt][nt], ahi[mt], bhi[nt]);  // hi*hi
                    mma_tf32(acc[mt][nt], ahi[mt], blo[nt]);  // hi*lo
                    mma_tf32(acc[mt][nt], alo[mt], bhi[nt]);  // lo*hi
                }
        }
        __syncthreads();
    }

    // ---- epilogue: add bias, store float2 pairs ----
    #pragma unroll
    for (int mt = 0; mt < 4; mt++) {
        const int r0 = bm + wy * 64 + mt * 16 + lq;
        const int r1 = r0 + 8;
        #pragma unroll
        for (int nt = 0; nt < 4; nt++) {
            const int c = bn + wx * 32 + nt * 8 + lr * 2;
            const float2 bv = *(const float2*)(bias + c);
            if (r0 < M) {
                float2 o0 = make_float2(acc[mt][nt][0] + bv.x, acc[mt][nt][1] + bv.y);
                *(float2*)(C + (size_t)r0 * N + c) = o0;
            }
            if (r1 < M) {
                float2 o1 = make_float2(acc[mt][nt][2] + bv.x, acc[mt][nt][3] + bv.y);
                *(float2*)(C + (size_t)r1 * N + c) = o1;
            }
        }
    }
}

// ---------------- fused softmax + location + bilinear sampling ----------------
// One warp per (b, q, h). Lane = output channel (HD=32).
// Lanes 0..15 precompute corner offsets + premultiplied weights into smem;
// shuffle mask must be 0xffff (only lanes 0..15 execute the shuffles).
__global__ __launch_bounds__(256)
void msda_sample(const float* __restrict__ v,     // [BS, LV, EMBED]
                 const float* __restrict__ offr,  // [BS, LQ, EMBED]  (NH,SUMP,2)
                 const float* __restrict__ attnl, // [BS, LQ, NH*SUMP]
                 const float* __restrict__ refp,  // [BS, LQ, 4]
                 float* __restrict__ mid)         // [BS, LQ, EMBED]
{
    __shared__ int4   s_idx[8][SUMP];
    __shared__ float4 s_w  [8][SUMP];

    const unsigned HALF = 0x0000ffffu;   // lanes 0..15 only
    const int lane = threadIdx.x & 31;
    const int warp = threadIdx.x >> 5;
    const int wid  = (blockIdx.x * blockDim.x + threadIdx.x) >> 5;
    const int h = wid & (NH - 1);
    const int q = (wid >> 3) & (LQ - 1);
    const int b = wid >> 15;

    if (lane < SUMP) {
        const float4 ref = *(const float4*)(refp + ((size_t)b * LQ + q) * 4);
        const float* ob = offr + ((size_t)b * LQ + q) * EMBED + (h * SUMP + lane) * 2;
        const float offx = ob[0];
        const float offy = ob[1];
        const float logit = attnl[((size_t)b * LQ + q) * (NH * SUMP) + h * SUMP + lane];

        float m = logit;
        #pragma unroll
        for (int s = 8; s > 0; s >>= 1) m = fmaxf(m, __shfl_xor_sync(HALF, m, s));
        float e = __expf(logit - m);
        float ssum = e;
        #pragma unroll
        for (int s = 8; s > 0; s >>= 1) ssum += __shfl_xor_sync(HALF, ssum, s);
        const float pw = e / ssum;

        const float cx = ref.x + offx * 0.125f * ref.z;
        const float cy = ref.y + offy * 0.125f * ref.w;

        const int l  = lane >> 2;
        const int Wl = 80 >> l, Hl = 80 >> l;            // 80,40,20,10
        const int vs = (l == 0) ? 0 : (l == 1) ? 6400 : (l == 2) ? 8000 : 8400;

        const float x = cx * (float)Wl - 0.5f;
        const float y = cy * (float)Hl - 0.5f;
        const float x0f = floorf(x), y0f = floorf(y);
        const int x0 = (int)x0f, y0 = (int)y0f;
        const float lx = x - x0f, ly = y - y0f;

        const float vx0 = (x0 >= 0 && x0 < Wl)         ? 1.f : 0.f;
        const float vx1 = (x0 + 1 >= 0 && x0 + 1 < Wl) ? 1.f : 0.f;
        const float vy0 = (y0 >= 0 && y0 < Hl)         ? 1.f : 0.f;
        const float vy1 = (y0 + 1 >= 0 && y0 + 1 < Hl) ? 1.f : 0.f;

        const int xc0 = min(max(x0, 0), Wl - 1);
        const int xc1 = min(max(x0 + 1, 0), Wl - 1);
        const int yc0 = min(max(y0, 0), Hl - 1);
        const int yc1 = min(max(y0 + 1, 0), Hl - 1);

        int4 idx;
        idx.x = (vs + yc0 * Wl + xc0) * EMBED;
        idx.y = (vs + yc0 * Wl + xc1) * EMBED;
        idx.z = (vs + yc1 * Wl + xc0) * EMBED;
        idx.w = (vs + yc1 * Wl + xc1) * EMBED;

        float4 ww;
        ww.x = (1.f - lx) * (1.f - ly) * pw * (vx0 * vy0);
        ww.y = lx * (1.f - ly) * pw * (vx1 * vy0);
        ww.z = (1.f - lx) * ly * pw * (vx0 * vy1);
        ww.w = lx * ly * pw * (vx1 * vy1);

        s_idx[warp][lane] = idx;
        s_w  [warp][lane] = ww;
    }
    __syncwarp();

    const float* vb = v + (size_t)b * LV * EMBED + h * HD + lane; // lane = channel
    float acc = 0.f;

    #pragma unroll
    for (int p = 0; p < SUMP; p++) {
        const int4   id = s_idx[warp][p];
        const float4 ww = s_w  [warp][p];
        acc = fmaf(ww.x, __ldg(vb + id.x), acc);
        acc = fmaf(ww.y, __ldg(vb + id.y), acc);
        acc = fmaf(ww.z, __ldg(vb + id.z), acc);
        acc = fmaf(ww.w, __ldg(vb + id.w), acc);
    }

    mid[((size_t)b * LQ + q) * EMBED + h * HD + lane] = acc;
}

// ---------------- launch ----------------
extern "C" void kernel_launch(void* const* d_in, const int* in_sizes, int n_in,
                              void* d_out, int out_size)
{
    const float* query  = (const float*)d_in[0];
    const float* refp   = (const float*)d_in[1];
    const float* value  = (const float*)d_in[2];
    const float* W_off  = (const float*)d_in[3];
    const float* b_off  = (const float*)d_in[4];
    const float* W_attn = (const float*)d_in[5];
    const float* b_attn = (const float*)d_in[6];
    const float* W_v    = (const float*)d_in[7];
    const float* b_v    = (const float*)d_in[8];
    const float* W_o    = (const float*)d_in[9];
    const float* b_o    = (const float*)d_in[10];
    float* out = (float*)d_out;

    float *gv, *goff, *gattn, *gmid;
    cudaGetSymbolAddress((void**)&gv,    g_v);
    cudaGetSymbolAddress((void**)&goff,  g_off);
    cudaGetSymbolAddress((void**)&gattn, g_attn);
    cudaGetSymbolAddress((void**)&gmid,  g_mid);

    const int MV = BS * LV;   // 34000
    const int MQ = BS * LQ;   // 16384

    // 1) v = value @ W_v + b_v          [34000, 256]
    gemm_3xtf32_bias<<<dim3(EMBED / BN, (MV + BM - 1) / BM), 256>>>(
        value, W_v, b_v, gv, MV, EMBED, EMBED);

    // 2) off = query @ W_off + b_off    [16384, 256]
    gemm_3xtf32_bias<<<dim3(EMBED / BN, MQ / BM), 256>>>(
        query, W_off, b_off, goff, MQ, EMBED, EMBED);

    // 3) attn logits = query @ W_attn + b_attn   [16384, 128]
    gemm_3xtf32_bias<<<dim3((NH * SUMP) / BN, MQ / BM), 256>>>(
        query, W_attn, b_attn, gattn, MQ, NH * SUMP, EMBED);

    // 4) fused softmax + bilinear sampling -> g_mid [16384, 256]
    {
        const int total_warps = BS * LQ * NH;          // 131072
        const int threads = 256;                        // 8 warps/block
        const int blocks = total_warps / (threads / 32);
        msda_sample<<<blocks, threads>>>(gv, goff, gattn, refp, gmid);
    }

    // 5) out = g_mid @ W_o + b_o        [16384, 256]
    gemm_3xtf32_bias<<<dim3(EMBED / BN, MQ / BM), 256>>>(
        gmid, W_o, b_o, out, MQ, EMBED, EMBED);
}